// round 1
// baseline (speedup 1.0000x reference)
#include <cuda_runtime.h>
#include <math.h>

#define S_LEN 2048
#define D_MODEL 512
#define N_HEADS 8
#define D_K 64
#define WINDOW 64
#define SCALE 0.125f   // 1/sqrt(64)

// ---------------- scratch (no allocation allowed) ----------------
__device__ float g_q[S_LEN * D_MODEL];
__device__ float g_k[S_LEN * D_MODEL];
__device__ float g_v[S_LEN * D_MODEL];
__device__ float g_attn[S_LEN * D_MODEL];

// ---------------- GEMM: C[M,N] = A[M,K] @ B[N,K]^T + bias[N] ----------------
// A row-major [M,K], B row-major [N,K] (so both read contiguous along K).
#define BM 128
#define BN 128
#define BK 16
#define TM 8
#define TN 8

__global__ __launch_bounds__(256)
void gemm_nt_bias(const float* __restrict__ A, const float* __restrict__ B,
                  const float* __restrict__ bias, float* __restrict__ C,
                  int M, int N, int K) {
    __shared__ float As[BK][BM + 4];
    __shared__ float Bs[BK][BN + 4];

    const int tid = threadIdx.x;
    const int tx = tid & 15;        // 0..15 (col group)
    const int ty = tid >> 4;        // 0..15 (row group)
    const int rowBase = blockIdx.y * BM;
    const int colBase = blockIdx.x * BN;

    // loader indexing: 4 threads per row, each loads a float4 along K
    const int la_row = tid >> 2;        // 0..63
    const int la_k   = (tid & 3) * 4;   // 0,4,8,12

    float acc[TM][TN];
#pragma unroll
    for (int i = 0; i < TM; i++)
#pragma unroll
        for (int j = 0; j < TN; j++) acc[i][j] = 0.f;

    for (int k0 = 0; k0 < K; k0 += BK) {
#pragma unroll
        for (int i = 0; i < 2; i++) {
            int r = la_row + i * 64;
            float4 va = *reinterpret_cast<const float4*>(&A[(size_t)(rowBase + r) * K + k0 + la_k]);
            As[la_k + 0][r] = va.x; As[la_k + 1][r] = va.y;
            As[la_k + 2][r] = va.z; As[la_k + 3][r] = va.w;
            float4 vb = *reinterpret_cast<const float4*>(&B[(size_t)(colBase + r) * K + k0 + la_k]);
            Bs[la_k + 0][r] = vb.x; Bs[la_k + 1][r] = vb.y;
            Bs[la_k + 2][r] = vb.z; Bs[la_k + 3][r] = vb.w;
        }
        __syncthreads();

#pragma unroll
        for (int kk = 0; kk < BK; kk++) {
            float a[TM], b[TN];
            const float4* ar = reinterpret_cast<const float4*>(&As[kk][ty * TM]);
            float4 a0 = ar[0], a1 = ar[1];
            a[0] = a0.x; a[1] = a0.y; a[2] = a0.z; a[3] = a0.w;
            a[4] = a1.x; a[5] = a1.y; a[6] = a1.z; a[7] = a1.w;
            const float4* br = reinterpret_cast<const float4*>(&Bs[kk][tx * TN]);
            float4 b0 = br[0], b1 = br[1];
            b[0] = b0.x; b[1] = b0.y; b[2] = b0.z; b[3] = b0.w;
            b[4] = b1.x; b[5] = b1.y; b[6] = b1.z; b[7] = b1.w;
#pragma unroll
            for (int i = 0; i < TM; i++)
#pragma unroll
                for (int j = 0; j < TN; j++)
                    acc[i][j] = fmaf(a[i], b[j], acc[i][j]);
        }
        __syncthreads();
    }

#pragma unroll
    for (int i = 0; i < TM; i++) {
        int row = rowBase + ty * TM + i;
#pragma unroll
        for (int j = 0; j < TN; j++) {
            int col = colBase + tx * TN + j;
            C[(size_t)row * N + col] = acc[i][j] + bias[col];
        }
    }
}

// ---------------- banded attention ----------------
// grid: (S/QT, N_HEADS), block 256 (8 warps), QT=64 queries per block.
// Key window for the tile: [base-64, base+127] => 192 rows.
#define QT 64
#define KEYS 192
#define ATTN_SMEM (2 * KEYS * D_K * sizeof(float))   // 96 KB

__global__ __launch_bounds__(256)
void attn_banded(const float* __restrict__ q, const float* __restrict__ k,
                 const float* __restrict__ v, float* __restrict__ o) {
    extern __shared__ float sm[];
    float* Ks = sm;                 // [KEYS][64]
    float* Vs = sm + KEYS * D_K;    // [KEYS][64]

    const int h = blockIdx.y;
    const int base = blockIdx.x * QT;
    const int j0 = base - WINDOW;

    for (int idx = threadIdx.x; idx < KEYS * D_K; idx += 256) {
        int r = idx >> 6;
        int d = idx & 63;
        int j = j0 + r;
        bool ok = (j >= 0) && (j < S_LEN);
        size_t g = (size_t)j * D_MODEL + h * D_K + d;
        Ks[idx] = ok ? k[g] : 0.f;
        Vs[idx] = ok ? v[g] : 0.f;
    }
    __syncthreads();

    const int warp = threadIdx.x >> 5;
    const int lane = threadIdx.x & 31;

    for (int ql = warp; ql < QT; ql += 8) {
        const int s = base + ql;
        const float q0 = q[(size_t)s * D_MODEL + h * D_K + lane];
        const float q1 = q[(size_t)s * D_MODEL + h * D_K + lane + 32];
        const int jlo = (s - WINDOW > 0) ? (s - WINDOW) : 0;
        const int jhi = (s + WINDOW < S_LEN - 1) ? (s + WINDOW) : (S_LEN - 1);

        float m = -1e30f, l = 0.f, a0 = 0.f, a1 = 0.f;
        for (int j = jlo; j <= jhi; j++) {
            const int r = j - j0;
            float p = q0 * Ks[r * D_K + lane] + q1 * Ks[r * D_K + lane + 32];
            p += __shfl_xor_sync(0xffffffffu, p, 16);
            p += __shfl_xor_sync(0xffffffffu, p, 8);
            p += __shfl_xor_sync(0xffffffffu, p, 4);
            p += __shfl_xor_sync(0xffffffffu, p, 2);
            p += __shfl_xor_sync(0xffffffffu, p, 1);
            const float sc = p * SCALE;
            const float mn = fmaxf(m, sc);
            const float corr = __expf(m - mn);
            const float e = __expf(sc - mn);
            l = l * corr + e;
            a0 = fmaf(a0, corr, e * Vs[r * D_K + lane]);
            a1 = fmaf(a1, corr, e * Vs[r * D_K + lane + 32]);
            m = mn;
        }
        const float inv = 1.f / l;
        o[(size_t)s * D_MODEL + h * D_K + lane] = a0 * inv;
        o[(size_t)s * D_MODEL + h * D_K + lane + 32] = a1 * inv;
    }
}

// ---------------- launch ----------------
extern "C" void kernel_launch(void* const* d_in, const int* in_sizes, int n_in,
                              void* d_out, int out_size) {
    const float* x  = (const float*)d_in[0];
    const float* Wq = (const float*)d_in[1];
    const float* bq = (const float*)d_in[2];
    const float* Wk = (const float*)d_in[3];
    const float* bk = (const float*)d_in[4];
    const float* Wv = (const float*)d_in[5];
    const float* bv = (const float*)d_in[6];
    const float* Wo = (const float*)d_in[7];
    const float* bo = (const float*)d_in[8];
    float* out = (float*)d_out;

    float *gq, *gk, *gv, *ga;
    cudaGetSymbolAddress((void**)&gq, g_q);
    cudaGetSymbolAddress((void**)&gk, g_k);
    cudaGetSymbolAddress((void**)&gv, g_v);
    cudaGetSymbolAddress((void**)&ga, g_attn);

    dim3 ggrid(D_MODEL / BN, S_LEN / BM);   // (4, 16)
    gemm_nt_bias<<<ggrid, 256>>>(x, Wq, bq, gq, S_LEN, D_MODEL, D_MODEL);
    gemm_nt_bias<<<ggrid, 256>>>(x, Wk, bk, gk, S_LEN, D_MODEL, D_MODEL);
    gemm_nt_bias<<<ggrid, 256>>>(x, Wv, bv, gv, S_LEN, D_MODEL, D_MODEL);

    cudaFuncSetAttribute(attn_banded, cudaFuncAttributeMaxDynamicSharedMemorySize,
                         (int)ATTN_SMEM);
    attn_banded<<<dim3(S_LEN / QT, N_HEADS), 256, ATTN_SMEM>>>(gq, gk, gv, ga);

    gemm_nt_bias<<<ggrid, 256>>>(ga, Wo, bo, out, S_LEN, D_MODEL, D_MODEL);
}

// round 2
// speedup vs baseline: 1.5776x; 1.5776x over previous
#include <cuda_runtime.h>
#include <math.h>

#define S_LEN 2048
#define D_MODEL 512
#define N_HEADS 8
#define D_K 64
#define WINDOW 64
#define SCALE 0.125f   // 1/sqrt(64)

// ---------------- scratch (no allocation allowed) ----------------
__device__ float g_q[S_LEN * D_MODEL];
__device__ float g_k[S_LEN * D_MODEL];
__device__ float g_v[S_LEN * D_MODEL];
__device__ float g_attn[S_LEN * D_MODEL];

// ---------------- GEMM body: C[M,N] = A[M,K] @ B[N,K]^T + bias[N] ----------
// Templated on tile so we can fill the chip for both the fused-QKV GEMM
// (N=1536 -> 192 CTAs) and the O GEMM (128x64 tiles -> 128 CTAs).
template<int BM, int BN, int NTHR>
__device__ __forceinline__ void gemm_body(
    const float* __restrict__ A, const float* __restrict__ B,
    const float* __restrict__ bias, float* __restrict__ C,
    int N, int K, int rowBase, int colBase)
{
    __shared__ float As[16][BM + 4];
    __shared__ float Bs[16][BN + 4];

    const int tid = threadIdx.x;
    const int BNT = BN / 8;
    const int tx = tid % BNT;
    const int ty = tid / BNT;

    float acc[8][8];
#pragma unroll
    for (int i = 0; i < 8; i++)
#pragma unroll
        for (int j = 0; j < 8; j++) acc[i][j] = 0.f;

    for (int k0 = 0; k0 < K; k0 += 16) {
#pragma unroll
        for (int i = tid; i < BM * 4; i += NTHR) {
            int r = i >> 2, kq = (i & 3) * 4;
            float4 va = *reinterpret_cast<const float4*>(
                &A[(size_t)(rowBase + r) * K + k0 + kq]);
            As[kq + 0][r] = va.x; As[kq + 1][r] = va.y;
            As[kq + 2][r] = va.z; As[kq + 3][r] = va.w;
        }
#pragma unroll
        for (int i = tid; i < BN * 4; i += NTHR) {
            int r = i >> 2, kq = (i & 3) * 4;
            float4 vb = *reinterpret_cast<const float4*>(
                &B[(size_t)(colBase + r) * K + k0 + kq]);
            Bs[kq + 0][r] = vb.x; Bs[kq + 1][r] = vb.y;
            Bs[kq + 2][r] = vb.z; Bs[kq + 3][r] = vb.w;
        }
        __syncthreads();

#pragma unroll
        for (int kk = 0; kk < 16; kk++) {
            float a[8], b[8];
            const float4* ar = reinterpret_cast<const float4*>(&As[kk][ty * 8]);
            float4 a0 = ar[0], a1 = ar[1];
            a[0]=a0.x; a[1]=a0.y; a[2]=a0.z; a[3]=a0.w;
            a[4]=a1.x; a[5]=a1.y; a[6]=a1.z; a[7]=a1.w;
            const float4* br = reinterpret_cast<const float4*>(&Bs[kk][tx * 8]);
            float4 b0 = br[0], b1 = br[1];
            b[0]=b0.x; b[1]=b0.y; b[2]=b0.z; b[3]=b0.w;
            b[4]=b1.x; b[5]=b1.y; b[6]=b1.z; b[7]=b1.w;
#pragma unroll
            for (int i = 0; i < 8; i++)
#pragma unroll
                for (int j = 0; j < 8; j++)
                    acc[i][j] = fmaf(a[i], b[j], acc[i][j]);
        }
        __syncthreads();
    }

#pragma unroll
    for (int i = 0; i < 8; i++) {
        int row = rowBase + ty * 8 + i;
#pragma unroll
        for (int j = 0; j < 8; j++) {
            int col = colBase + tx * 8 + j;
            C[(size_t)row * N + col] = acc[i][j] + bias[col];
        }
    }
}

// Fused QKV projection: one launch, 192 CTAs (12 x 16).
__global__ __launch_bounds__(256)
void gemm_qkv(const float* __restrict__ x,
              const float* __restrict__ Wq, const float* __restrict__ bq,
              const float* __restrict__ Wk, const float* __restrict__ bk,
              const float* __restrict__ Wv, const float* __restrict__ bv,
              float* __restrict__ q, float* __restrict__ k, float* __restrict__ v)
{
    const int which = blockIdx.x >> 2;          // 4 col-blocks of 128 per matrix
    const int colBase = (blockIdx.x & 3) * 128;
    const float* B   = (which == 0) ? Wq : (which == 1) ? Wk : Wv;
    const float* bia = (which == 0) ? bq : (which == 1) ? bk : bv;
    float*       C   = (which == 0) ? q  : (which == 1) ? k  : v;
    gemm_body<128, 128, 256>(x, B, bia, C, D_MODEL, D_MODEL,
                             blockIdx.y * 128, colBase);
}

// O projection: 128x64 tiles -> 128 CTAs (8 x 16).
__global__ __launch_bounds__(128)
void gemm_o(const float* __restrict__ A, const float* __restrict__ W,
            const float* __restrict__ bias, float* __restrict__ C)
{
    gemm_body<128, 64, 128>(A, W, bias, C, D_MODEL, D_MODEL,
                            blockIdx.y * 128, blockIdx.x * 64);
}

// ---------------- banded attention, two-pass key-per-lane ----------------
// Block: 128 threads (4 warps), QT=32 queries, each warp owns queries
// warp, warp+4, ... Keys window for the block: [base-64, base+QT-1+64].
// K rows padded to 192 (zero-filled) so the unconditional 5-slot dot
// reads stay in bounds; invalid slots are masked to -inf before softmax.
#define QT 32
#define KROWS 192
#define KSTRIDE 65
#define ATTN_SMEM ((KROWS * KSTRIDE + KROWS * 64 + QT * 64) * sizeof(float))

__global__ __launch_bounds__(128)
void attn_banded(const float* __restrict__ q, const float* __restrict__ k,
                 const float* __restrict__ v, float* __restrict__ o)
{
    extern __shared__ float sm[];
    float* Ks = sm;                               // [192][65]
    float* Vs = sm + KROWS * KSTRIDE;             // [192][64]
    float* Qs = Vs + KROWS * 64;                  // [QT][64]

    const int h = blockIdx.y;
    const int base = blockIdx.x * QT;
    const int j0 = base - WINDOW;
    const int tid = threadIdx.x;

    // stage K (padded stride 65) and V (stride 64), zero-fill OOB rows
    for (int idx = tid; idx < KROWS * 16; idx += 128) {
        int r = idx >> 4, d4 = (idx & 15) * 4;
        int j = j0 + r;
        float4 kv = make_float4(0.f, 0.f, 0.f, 0.f);
        float4 vv = make_float4(0.f, 0.f, 0.f, 0.f);
        if (j >= 0 && j < S_LEN) {
            size_t g = (size_t)j * D_MODEL + h * D_K + d4;
            kv = *reinterpret_cast<const float4*>(&k[g]);
            vv = *reinterpret_cast<const float4*>(&v[g]);
        }
        float* kd = &Ks[r * KSTRIDE + d4];
        kd[0] = kv.x; kd[1] = kv.y; kd[2] = kv.z; kd[3] = kv.w;
        *reinterpret_cast<float4*>(&Vs[r * 64 + d4]) = vv;
    }
    for (int idx = tid; idx < QT * 16; idx += 128) {
        int ql = idx >> 4, d4 = (idx & 15) * 4;
        *reinterpret_cast<float4*>(&Qs[ql * 64 + d4]) =
            *reinterpret_cast<const float4*>(&q[(size_t)(base + ql) * D_MODEL + h * D_K + d4]);
    }
    __syncthreads();

    const int warp = tid >> 5;
    const int lane = tid & 31;

    for (int ql = warp; ql < QT; ql += 4) {
        const int s = base + ql;
        const int jlo = (s - WINDOW > 0) ? (s - WINDOW) : 0;
        const int jhi = (s + WINDOW < S_LEN - 1) ? (s + WINDOW) : (S_LEN - 1);
        const int nk = jhi - jlo + 1;
        const int rbase = jlo - j0;

        // ---- phase 1: 5 key-slots per lane, full 64-dim dots ----
        float s0 = 0.f, s1 = 0.f, s2 = 0.f, s3 = 0.f, s4 = 0.f;
        const float* kr = &Ks[(rbase + lane) * KSTRIDE];
        const float* qr = &Qs[ql * 64];
#pragma unroll 8
        for (int d = 0; d < 64; d++) {
            float qv = qr[d];
            s0 = fmaf(qv, kr[d], s0);
            s1 = fmaf(qv, kr[32 * KSTRIDE + d], s1);
            s2 = fmaf(qv, kr[64 * KSTRIDE + d], s2);
            s3 = fmaf(qv, kr[96 * KSTRIDE + d], s3);
            s4 = fmaf(qv, kr[128 * KSTRIDE + d], s4);
        }
        float sc[5] = { s0, s1, s2, s3, s4 };
        float m = -1e30f;
#pragma unroll
        for (int i = 0; i < 5; i++) {
            sc[i] = (lane + 32 * i < nk) ? sc[i] * SCALE : -1e30f;
            m = fmaxf(m, sc[i]);
        }
#pragma unroll
        for (int off = 16; off; off >>= 1)
            m = fmaxf(m, __shfl_xor_sync(0xffffffffu, m, off));
        float e[5];
        float l = 0.f;
#pragma unroll
        for (int i = 0; i < 5; i++) { e[i] = __expf(sc[i] - m); l += e[i]; }
#pragma unroll
        for (int off = 16; off; off >>= 1)
            l += __shfl_xor_sync(0xffffffffu, l, off);
        const float inv = 1.f / l;

        // ---- phase 2: weighted V accumulation ----
        float a0 = 0.f, a1 = 0.f, b0 = 0.f, b1 = 0.f;
        const float* vb = &Vs[rbase * 64];
        if (nk == 129) {
#pragma unroll
            for (int slot = 0; slot < 4; slot++) {
                float ev = e[slot];
#pragma unroll
                for (int jj = 0; jj < 32; jj += 2) {
                    float p0 = __shfl_sync(0xffffffffu, ev, jj);
                    float p1 = __shfl_sync(0xffffffffu, ev, jj + 1);
                    const float* v0 = vb + (slot * 32 + jj) * 64;
                    a0 = fmaf(p0, v0[lane], a0);
                    a1 = fmaf(p0, v0[lane + 32], a1);
                    b0 = fmaf(p1, v0[64 + lane], b0);
                    b1 = fmaf(p1, v0[64 + lane + 32], b1);
                }
            }
            float p = __shfl_sync(0xffffffffu, e[4], 0);
            const float* v0 = vb + 128 * 64;
            a0 = fmaf(p, v0[lane], a0);
            a1 = fmaf(p, v0[lane + 32], a1);
        } else {
#pragma unroll
            for (int slot = 0; slot < 5; slot++) {
                int lim = nk - slot * 32;
                if (lim <= 0) break;
                if (lim > 32) lim = 32;
                float ev = e[slot];
                for (int jj = 0; jj < lim; jj++) {
                    float p = __shfl_sync(0xffffffffu, ev, jj);
                    const float* v0 = vb + (slot * 32 + jj) * 64;
                    a0 = fmaf(p, v0[lane], a0);
                    a1 = fmaf(p, v0[lane + 32], a1);
                }
            }
        }
        o[(size_t)s * D_MODEL + h * D_K + lane]      = (a0 + b0) * inv;
        o[(size_t)s * D_MODEL + h * D_K + lane + 32] = (a1 + b1) * inv;
    }
}

// ---------------- launch ----------------
extern "C" void kernel_launch(void* const* d_in, const int* in_sizes, int n_in,
                              void* d_out, int out_size) {
    const float* x  = (const float*)d_in[0];
    const float* Wq = (const float*)d_in[1];
    const float* bq = (const float*)d_in[2];
    const float* Wk = (const float*)d_in[3];
    const float* bk = (const float*)d_in[4];
    const float* Wv = (const float*)d_in[5];
    const float* bv = (const float*)d_in[6];
    const float* Wo = (const float*)d_in[7];
    const float* bo = (const float*)d_in[8];
    float* out = (float*)d_out;

    float *gq, *gk, *gv, *ga;
    cudaGetSymbolAddress((void**)&gq, g_q);
    cudaGetSymbolAddress((void**)&gk, g_k);
    cudaGetSymbolAddress((void**)&gv, g_v);
    cudaGetSymbolAddress((void**)&ga, g_attn);

    gemm_qkv<<<dim3(12, 16), 256>>>(x, Wq, bq, Wk, bk, Wv, bv, gq, gk, gv);

    cudaFuncSetAttribute(attn_banded, cudaFuncAttributeMaxDynamicSharedMemorySize,
                         (int)ATTN_SMEM);
    attn_banded<<<dim3(S_LEN / QT, N_HEADS), 128, ATTN_SMEM>>>(gq, gk, gv, ga);

    gemm_o<<<dim3(8, 16), 128>>>(ga, Wo, bo, out);
}

// round 3
// speedup vs baseline: 1.9862x; 1.2590x over previous
#include <cuda_runtime.h>
#include <math.h>

#define S_LEN 2048
#define D_MODEL 512
#define N_HEADS 8
#define D_K 64
#define WINDOW 64
#define SCALE 0.125f   // 1/sqrt(64)

// ---------------- scratch (no allocation allowed) ----------------
__device__ float g_q[S_LEN * D_MODEL];
__device__ float g_k[S_LEN * D_MODEL];
__device__ float g_v[S_LEN * D_MODEL];
__device__ float g_attn[S_LEN * D_MODEL];

// ---------------- packed f32x2 helpers (sm_103a) ----------------
typedef unsigned long long u64t;

__device__ __forceinline__ u64t pack2(float lo, float hi) {
    u64t r; asm("mov.b64 %0, {%1, %2};" : "=l"(r) : "f"(lo), "f"(hi)); return r;
}
__device__ __forceinline__ void fma2(u64t& d, u64t a, u64t b) {
    asm("fma.rn.f32x2 %0, %1, %2, %0;" : "+l"(d) : "l"(a), "l"(b));
}
__device__ __forceinline__ float2 unpack2(u64t v) {
    float2 f; asm("mov.b64 {%0, %1}, %2;" : "=f"(f.x), "=f"(f.y) : "l"(v)); return f;
}

// ---------------- GEMM body: C[M,N] = A[M,K] @ B[N,K]^T + bias[N] ----------
// f32x2 packed-FMA microkernel, 8x8 outputs/thread held as 8x4 f32x2 pairs.
// Register double-buffering of the global tile loads.
template<int BM, int BN, int NTHR>
__device__ __forceinline__ void gemm_body(
    const float* __restrict__ A, const float* __restrict__ B,
    const float* __restrict__ bias, float* __restrict__ C,
    int N, int K, int rowBase, int colBase)
{
    __shared__ float As[16][BM + 4];
    __shared__ float Bs[16][BN + 4];

    const int tid = threadIdx.x;
    const int BNT = BN / 8;
    const int tx = tid % BNT;
    const int ty = tid / BNT;

    constexpr int LA = BM * 4 / NTHR;   // float4 A-loads per thread per tile
    constexpr int LB = BN * 4 / NTHR;

    float4 pa[LA], pb[LB];

    // prefetch tile 0
#pragma unroll
    for (int i = 0; i < LA; i++) {
        int t = tid + i * NTHR; int r = t >> 2, kq = (t & 3) * 4;
        pa[i] = *reinterpret_cast<const float4*>(&A[(size_t)(rowBase + r) * K + kq]);
    }
#pragma unroll
    for (int i = 0; i < LB; i++) {
        int t = tid + i * NTHR; int r = t >> 2, kq = (t & 3) * 4;
        pb[i] = *reinterpret_cast<const float4*>(&B[(size_t)(colBase + r) * K + kq]);
    }

    u64t acc[8][4];
#pragma unroll
    for (int i = 0; i < 8; i++)
#pragma unroll
        for (int j = 0; j < 4; j++) acc[i][j] = 0ull;

    for (int k0 = 0; k0 < K; k0 += 16) {
        // commit prefetched tile to smem
#pragma unroll
        for (int i = 0; i < LA; i++) {
            int t = tid + i * NTHR; int r = t >> 2, kq = (t & 3) * 4;
            As[kq + 0][r] = pa[i].x; As[kq + 1][r] = pa[i].y;
            As[kq + 2][r] = pa[i].z; As[kq + 3][r] = pa[i].w;
        }
#pragma unroll
        for (int i = 0; i < LB; i++) {
            int t = tid + i * NTHR; int r = t >> 2, kq = (t & 3) * 4;
            Bs[kq + 0][r] = pb[i].x; Bs[kq + 1][r] = pb[i].y;
            Bs[kq + 2][r] = pb[i].z; Bs[kq + 3][r] = pb[i].w;
        }
        __syncthreads();

        // issue next-tile LDGs (latency hidden by the FMA block below)
        if (k0 + 16 < K) {
#pragma unroll
            for (int i = 0; i < LA; i++) {
                int t = tid + i * NTHR; int r = t >> 2, kq = (t & 3) * 4;
                pa[i] = *reinterpret_cast<const float4*>(
                    &A[(size_t)(rowBase + r) * K + k0 + 16 + kq]);
            }
#pragma unroll
            for (int i = 0; i < LB; i++) {
                int t = tid + i * NTHR; int r = t >> 2, kq = (t & 3) * 4;
                pb[i] = *reinterpret_cast<const float4*>(
                    &B[(size_t)(colBase + r) * K + k0 + 16 + kq]);
            }
        }

#pragma unroll
        for (int kk = 0; kk < 16; kk++) {
            const float4* ar = reinterpret_cast<const float4*>(&As[kk][ty * 8]);
            float4 a0 = ar[0], a1 = ar[1];
            const float4* br = reinterpret_cast<const float4*>(&Bs[kk][tx * 8]);
            float4 b0 = br[0], b1 = br[1];

            u64t b2[4];
            b2[0] = pack2(b0.x, b0.y); b2[1] = pack2(b0.z, b0.w);
            b2[2] = pack2(b1.x, b1.y); b2[3] = pack2(b1.z, b1.w);
            u64t a2[8];
            a2[0] = pack2(a0.x, a0.x); a2[1] = pack2(a0.y, a0.y);
            a2[2] = pack2(a0.z, a0.z); a2[3] = pack2(a0.w, a0.w);
            a2[4] = pack2(a1.x, a1.x); a2[5] = pack2(a1.y, a1.y);
            a2[6] = pack2(a1.z, a1.z); a2[7] = pack2(a1.w, a1.w);

#pragma unroll
            for (int i = 0; i < 8; i++)
#pragma unroll
                for (int j = 0; j < 4; j++)
                    fma2(acc[i][j], a2[i], b2[j]);
        }
        __syncthreads();
    }

    // epilogue: add bias, store as float4
#pragma unroll
    for (int i = 0; i < 8; i++) {
        int row = rowBase + ty * 8 + i;
        int col = colBase + tx * 8;
        float2 c0 = unpack2(acc[i][0]), c1 = unpack2(acc[i][1]);
        float2 c2 = unpack2(acc[i][2]), c3 = unpack2(acc[i][3]);
        float4 o0 = make_float4(c0.x + bias[col + 0], c0.y + bias[col + 1],
                                c1.x + bias[col + 2], c1.y + bias[col + 3]);
        float4 o1 = make_float4(c2.x + bias[col + 4], c2.y + bias[col + 5],
                                c3.x + bias[col + 6], c3.y + bias[col + 7]);
        *reinterpret_cast<float4*>(&C[(size_t)row * N + col]) = o0;
        *reinterpret_cast<float4*>(&C[(size_t)row * N + col + 4]) = o1;
    }
}

// Fused QKV projection: one launch, 192 CTAs (12 x 16).
__global__ __launch_bounds__(256)
void gemm_qkv(const float* __restrict__ x,
              const float* __restrict__ Wq, const float* __restrict__ bq,
              const float* __restrict__ Wk, const float* __restrict__ bk,
              const float* __restrict__ Wv, const float* __restrict__ bv,
              float* __restrict__ q, float* __restrict__ k, float* __restrict__ v)
{
    const int which = blockIdx.x >> 2;
    const int colBase = (blockIdx.x & 3) * 128;
    const float* B   = (which == 0) ? Wq : (which == 1) ? Wk : Wv;
    const float* bia = (which == 0) ? bq : (which == 1) ? bk : bv;
    float*       C   = (which == 0) ? q  : (which == 1) ? k  : v;
    gemm_body<128, 128, 256>(x, B, bia, C, D_MODEL, D_MODEL,
                             blockIdx.y * 128, colBase);
}

// O projection: 128x64 tiles -> 128 CTAs (8 x 16).
__global__ __launch_bounds__(128)
void gemm_o(const float* __restrict__ A, const float* __restrict__ W,
            const float* __restrict__ bias, float* __restrict__ C)
{
    gemm_body<128, 64, 128>(A, W, bias, C, D_MODEL, D_MODEL,
                            blockIdx.y * 128, blockIdx.x * 64);
}

// ---------------- banded attention, two-pass key-per-lane ----------------
#define QT 32
#define KROWS 192
#define KSTRIDE 65
#define ATTN_SMEM ((KROWS * KSTRIDE + KROWS * 64 + QT * 64) * sizeof(float))

__global__ __launch_bounds__(128)
void attn_banded(const float* __restrict__ q, const float* __restrict__ k,
                 const float* __restrict__ v, float* __restrict__ o)
{
    extern __shared__ float sm[];
    float* Ks = sm;                               // [192][65]
    float* Vs = sm + KROWS * KSTRIDE;             // [192][64]
    float* Qs = Vs + KROWS * 64;                  // [QT][64]

    const int h = blockIdx.y;
    const int base = blockIdx.x * QT;
    const int j0 = base - WINDOW;
    const int tid = threadIdx.x;

    for (int idx = tid; idx < KROWS * 16; idx += 128) {
        int r = idx >> 4, d4 = (idx & 15) * 4;
        int j = j0 + r;
        float4 kv = make_float4(0.f, 0.f, 0.f, 0.f);
        float4 vv = make_float4(0.f, 0.f, 0.f, 0.f);
        if (j >= 0 && j < S_LEN) {
            size_t g = (size_t)j * D_MODEL + h * D_K + d4;
            kv = *reinterpret_cast<const float4*>(&k[g]);
            vv = *reinterpret_cast<const float4*>(&v[g]);
        }
        float* kd = &Ks[r * KSTRIDE + d4];
        kd[0] = kv.x; kd[1] = kv.y; kd[2] = kv.z; kd[3] = kv.w;
        *reinterpret_cast<float4*>(&Vs[r * 64 + d4]) = vv;
    }
    for (int idx = tid; idx < QT * 16; idx += 128) {
        int ql = idx >> 4, d4 = (idx & 15) * 4;
        *reinterpret_cast<float4*>(&Qs[ql * 64 + d4]) =
            *reinterpret_cast<const float4*>(&q[(size_t)(base + ql) * D_MODEL + h * D_K + d4]);
    }
    __syncthreads();

    const int warp = tid >> 5;
    const int lane = tid & 31;

    for (int ql = warp; ql < QT; ql += 4) {
        const int s = base + ql;
        const int jlo = (s - WINDOW > 0) ? (s - WINDOW) : 0;
        const int jhi = (s + WINDOW < S_LEN - 1) ? (s + WINDOW) : (S_LEN - 1);
        const int nk = jhi - jlo + 1;
        const int rbase = jlo - j0;

        // ---- phase 1: 5 key-slots per lane, full 64-dim dots ----
        float s0 = 0.f, s1 = 0.f, s2 = 0.f, s3 = 0.f, s4 = 0.f;
        const float* kr = &Ks[(rbase + lane) * KSTRIDE];
        const float* qr = &Qs[ql * 64];
#pragma unroll 8
        for (int d = 0; d < 64; d++) {
            float qv = qr[d];
            s0 = fmaf(qv, kr[d], s0);
            s1 = fmaf(qv, kr[32 * KSTRIDE + d], s1);
            s2 = fmaf(qv, kr[64 * KSTRIDE + d], s2);
            s3 = fmaf(qv, kr[96 * KSTRIDE + d], s3);
            s4 = fmaf(qv, kr[128 * KSTRIDE + d], s4);
        }
        float sc[5] = { s0, s1, s2, s3, s4 };
        float m = -1e30f;
#pragma unroll
        for (int i = 0; i < 5; i++) {
            sc[i] = (lane + 32 * i < nk) ? sc[i] * SCALE : -1e30f;
            m = fmaxf(m, sc[i]);
        }
#pragma unroll
        for (int off = 16; off; off >>= 1)
            m = fmaxf(m, __shfl_xor_sync(0xffffffffu, m, off));
        float e[5];
        float l = 0.f;
#pragma unroll
        for (int i = 0; i < 5; i++) { e[i] = __expf(sc[i] - m); l += e[i]; }
#pragma unroll
        for (int off = 16; off; off >>= 1)
            l += __shfl_xor_sync(0xffffffffu, l, off);
        const float inv = 1.f / l;

        // ---- phase 2: weighted V accumulation ----
        float a0 = 0.f, a1 = 0.f, b0 = 0.f, b1 = 0.f;
        const float* vb = &Vs[rbase * 64];
        if (nk == 129) {
#pragma unroll
            for (int slot = 0; slot < 4; slot++) {
                float ev = e[slot];
#pragma unroll
                for (int jj = 0; jj < 32; jj += 2) {
                    float p0 = __shfl_sync(0xffffffffu, ev, jj);
                    float p1 = __shfl_sync(0xffffffffu, ev, jj + 1);
                    const float* v0 = vb + (slot * 32 + jj) * 64;
                    a0 = fmaf(p0, v0[lane], a0);
                    a1 = fmaf(p0, v0[lane + 32], a1);
                    b0 = fmaf(p1, v0[64 + lane], b0);
                    b1 = fmaf(p1, v0[64 + lane + 32], b1);
                }
            }
            float p = __shfl_sync(0xffffffffu, e[4], 0);
            const float* v0 = vb + 128 * 64;
            a0 = fmaf(p, v0[lane], a0);
            a1 = fmaf(p, v0[lane + 32], a1);
        } else {
#pragma unroll
            for (int slot = 0; slot < 5; slot++) {
                int lim = nk - slot * 32;
                if (lim <= 0) break;
                if (lim > 32) lim = 32;
                float ev = e[slot];
                for (int jj = 0; jj < lim; jj++) {
                    float p = __shfl_sync(0xffffffffu, ev, jj);
                    const float* v0 = vb + (slot * 32 + jj) * 64;
                    a0 = fmaf(p, v0[lane], a0);
                    a1 = fmaf(p, v0[lane + 32], a1);
                }
            }
        }
        o[(size_t)s * D_MODEL + h * D_K + lane]      = (a0 + b0) * inv;
        o[(size_t)s * D_MODEL + h * D_K + lane + 32] = (a1 + b1) * inv;
    }
}

// ---------------- launch ----------------
extern "C" void kernel_launch(void* const* d_in, const int* in_sizes, int n_in,
                              void* d_out, int out_size) {
    const float* x  = (const float*)d_in[0];
    const float* Wq = (const float*)d_in[1];
    const float* bq = (const float*)d_in[2];
    const float* Wk = (const float*)d_in[3];
    const float* bk = (const float*)d_in[4];
    const float* Wv = (const float*)d_in[5];
    const float* bv = (const float*)d_in[6];
    const float* Wo = (const float*)d_in[7];
    const float* bo = (const float*)d_in[8];
    float* out = (float*)d_out;

    float *gq, *gk, *gv, *ga;
    cudaGetSymbolAddress((void**)&gq, g_q);
    cudaGetSymbolAddress((void**)&gk, g_k);
    cudaGetSymbolAddress((void**)&gv, g_v);
    cudaGetSymbolAddress((void**)&ga, g_attn);

    gemm_qkv<<<dim3(12, 16), 256>>>(x, Wq, bq, Wk, bk, Wv, bv, gq, gk, gv);

    cudaFuncSetAttribute(attn_banded, cudaFuncAttributeMaxDynamicSharedMemorySize,
                         (int)ATTN_SMEM);
    attn_banded<<<dim3(S_LEN / QT, N_HEADS), 128, ATTN_SMEM>>>(gq, gk, gv, ga);

    gemm_o<<<dim3(8, 16), 128>>>(ga, Wo, bo, out);
}

// round 5
// speedup vs baseline: 3.0876x; 1.5545x over previous
#include <cuda_runtime.h>
#include <cuda_bf16.h>
#include <stdint.h>
#include <math.h>

#define S_LEN 2048
#define D_MODEL 512
#define N_HEADS 8
#define D_K 64
#define WINDOW 64
#define SCALE 0.125f   // 1/sqrt(64)
#define WSZ (512*512)
#define XSZ (2048*512)

// ---------------- scratch (no allocation allowed) ----------------
__device__ __align__(16) float g_q[XSZ];
__device__ __align__(16) float g_k[XSZ];
__device__ __align__(16) float g_v[XSZ];
__device__ __align__(16) __nv_bfloat16 g_x_hi[XSZ];
__device__ __align__(16) __nv_bfloat16 g_x_lo[XSZ];
__device__ __align__(16) __nv_bfloat16 g_w_hi[4 * WSZ];
__device__ __align__(16) __nv_bfloat16 g_w_lo[4 * WSZ];
__device__ __align__(16) __nv_bfloat16 g_a_hi[XSZ];
__device__ __align__(16) __nv_bfloat16 g_a_lo[XSZ];

// ---------------- PTX helpers (all baseline sm_80+ — compile for compute_103) ----
__device__ __forceinline__ uint32_t smem_u32(const void* p) {
    uint32_t a;
    asm("{ .reg .u64 t; cvta.to.shared.u64 t, %1; cvt.u32.u64 %0, t; }"
        : "=r"(a) : "l"(p));
    return a;
}
__device__ __forceinline__ void cp16(uint32_t s, const void* g) {
    asm volatile("cp.async.cg.shared.global [%0], [%1], 16;"
                 :: "r"(s), "l"(g) : "memory");
}
__device__ __forceinline__ void cp_commit() {
    asm volatile("cp.async.commit_group;" ::: "memory");
}
template<int N> __device__ __forceinline__ void cp_wait() {
    asm volatile("cp.async.wait_group %0;" :: "n"(N) : "memory");
}
__device__ __forceinline__ void ldsm_x4(uint32_t& r0, uint32_t& r1,
                                        uint32_t& r2, uint32_t& r3, uint32_t a) {
    asm volatile("ldmatrix.sync.aligned.m8n8.x4.shared.b16 {%0,%1,%2,%3}, [%4];"
                 : "=r"(r0), "=r"(r1), "=r"(r2), "=r"(r3) : "r"(a));
}
__device__ __forceinline__ void mma16816(float c[4], const uint32_t a[4],
                                         const uint32_t b[2]) {
    asm volatile(
        "mma.sync.aligned.m16n8k16.row.col.f32.bf16.bf16.f32 "
        "{%0,%1,%2,%3}, {%4,%5,%6,%7}, {%8,%9}, {%0,%1,%2,%3};"
        : "+f"(c[0]), "+f"(c[1]), "+f"(c[2]), "+f"(c[3])
        : "r"(a[0]), "r"(a[1]), "r"(a[2]), "r"(a[3]), "r"(b[0]), "r"(b[1]));
}

// ---------------- split conversion: fp32 -> (bf16 hi, bf16 lo) ----------------
__global__ __launch_bounds__(256)
void convert_split(const float* __restrict__ x,
                   const float* __restrict__ wq, const float* __restrict__ wk,
                   const float* __restrict__ wv, const float* __restrict__ wo)
{
    const int tn = blockIdx.y;
    const float* src = (tn == 0) ? x : (tn == 1) ? wq : (tn == 2) ? wk
                       : (tn == 3) ? wv : wo;
    const int n = (tn == 0) ? XSZ : WSZ;
    __nv_bfloat16* hi = (tn == 0) ? g_x_hi : g_w_hi + (tn - 1) * WSZ;
    __nv_bfloat16* lo = (tn == 0) ? g_x_lo : g_w_lo + (tn - 1) * WSZ;

    int i4 = (blockIdx.x * 256 + threadIdx.x) * 4;
    if (i4 >= n) return;
    float4 v = *reinterpret_cast<const float4*>(&src[i4]);
    __nv_bfloat16 h0 = __float2bfloat16(v.x);
    __nv_bfloat16 h1 = __float2bfloat16(v.y);
    __nv_bfloat16 h2 = __float2bfloat16(v.z);
    __nv_bfloat16 h3 = __float2bfloat16(v.w);
    __nv_bfloat16 l0 = __float2bfloat16(v.x - __bfloat162float(h0));
    __nv_bfloat16 l1 = __float2bfloat16(v.y - __bfloat162float(h1));
    __nv_bfloat16 l2 = __float2bfloat16(v.z - __bfloat162float(h2));
    __nv_bfloat16 l3 = __float2bfloat16(v.w - __bfloat162float(h3));
    reinterpret_cast<__nv_bfloat162*>(hi + i4)[0] = __halves2bfloat162(h0, h1);
    reinterpret_cast<__nv_bfloat162*>(hi + i4)[1] = __halves2bfloat162(h2, h3);
    reinterpret_cast<__nv_bfloat162*>(lo + i4)[0] = __halves2bfloat162(l0, l1);
    reinterpret_cast<__nv_bfloat162*>(lo + i4)[1] = __halves2bfloat162(l2, l3);
}

// ---------------- mma.sync split-bf16 GEMM: C[128,128] tile per CTA ------------
// C = Ah·Bh^T + Ah·Bl^T + Al·Bh^T + bias. A[m][512], B(=W)[n][512], bf16.
// SMEM tile: 128 rows x 64 bf16, rows padded to 144B (72 bf16) -> LDSM conflict-free.
#define ROWB 144
#define TILE_B (128 * ROWB)          // 18432
#define BUF_B  (4 * TILE_B)          // 73728: AH, AL, BH, BL
#define GSMEM  (2 * BUF_B)           // 147456, double-buffered

__device__ __forceinline__ void stage_chunk(
    uint32_t sb, int buf, int c, int tid,
    const __nv_bfloat16* const* srcs, const int* baseRow)
{
#pragma unroll
    for (int t = 0; t < 4; t++) {
#pragma unroll
        for (int i = 0; i < 4; i++) {
            int idx = tid + i * 256;
            int row = idx >> 3, c16 = idx & 7;
            const void* g = srcs[t] + ((size_t)(baseRow[t] + row) * 512 + c * 64 + c16 * 8);
            uint32_t s = sb + (uint32_t)(buf * BUF_B + t * TILE_B + row * ROWB + c16 * 16);
            cp16(s, g);
        }
    }
    cp_commit();
}

__device__ __forceinline__ void gemm_mma_body(
    const __nv_bfloat16* __restrict__ Ahi, const __nv_bfloat16* __restrict__ Alo,
    const __nv_bfloat16* __restrict__ Bhi, const __nv_bfloat16* __restrict__ Blo,
    const float* __restrict__ bias, float* __restrict__ Cout,
    int rowBase, int colBase)
{
    extern __shared__ __align__(16) char dynsm[];
    const uint32_t sb = smem_u32(dynsm);
    const int tid = threadIdx.x;
    const int lane = tid & 31, wid = tid >> 5;
    const int wm = wid >> 2, wn = wid & 3;

    const __nv_bfloat16* srcs[4] = { Ahi, Alo, Bhi, Blo };
    const int baseRow[4] = { rowBase, rowBase, colBase, colBase };

    float acc[4][4][4];
#pragma unroll
    for (int i = 0; i < 4; i++)
#pragma unroll
        for (int j = 0; j < 4; j++)
#pragma unroll
            for (int f = 0; f < 4; f++) acc[i][j][f] = 0.f;

    // ldmatrix lane geometry
    const int a_row = (lane & 7) + ((lane >> 3) & 1) * 8;   // m within m16
    const int a_k   = (lane >> 4) * 8;                       // k8 half
    const int b_row = (lane & 7) + (lane >> 4) * 8;          // n within n16
    const int b_k   = ((lane >> 3) & 1) * 8;

    stage_chunk(sb, 0, 0, tid, srcs, baseRow);

    for (int c = 0; c < 8; c++) {
        if (c < 7) { stage_chunk(sb, (c + 1) & 1, c + 1, tid, srcs, baseRow); cp_wait<1>(); }
        else       { cp_wait<0>(); }
        __syncthreads();

        const uint32_t bAH = sb + (uint32_t)((c & 1) * BUF_B);
        const uint32_t bAL = bAH + TILE_B;
        const uint32_t bBH = bAH + 2 * TILE_B;
        const uint32_t bBL = bAH + 3 * TILE_B;

#pragma unroll
        for (int k16 = 0; k16 < 4; k16++) {
            uint32_t ah[4][4], al[4][4], bh[4][2], bl[4][2];
#pragma unroll
            for (int mi = 0; mi < 4; mi++) {
                uint32_t off = (uint32_t)((wm * 64 + mi * 16 + a_row) * ROWB +
                                          (k16 * 16 + a_k) * 2);
                ldsm_x4(ah[mi][0], ah[mi][1], ah[mi][2], ah[mi][3], bAH + off);
                ldsm_x4(al[mi][0], al[mi][1], al[mi][2], al[mi][3], bAL + off);
            }
#pragma unroll
            for (int bn = 0; bn < 2; bn++) {
                uint32_t off = (uint32_t)((wn * 32 + bn * 16 + b_row) * ROWB +
                                          (k16 * 16 + b_k) * 2);
                uint32_t r0, r1, r2, r3;
                ldsm_x4(r0, r1, r2, r3, bBH + off);
                bh[bn * 2][0] = r0; bh[bn * 2][1] = r1;
                bh[bn * 2 + 1][0] = r2; bh[bn * 2 + 1][1] = r3;
                ldsm_x4(r0, r1, r2, r3, bBL + off);
                bl[bn * 2][0] = r0; bl[bn * 2][1] = r1;
                bl[bn * 2 + 1][0] = r2; bl[bn * 2 + 1][1] = r3;
            }
#pragma unroll
            for (int mi = 0; mi < 4; mi++)
#pragma unroll
                for (int ni = 0; ni < 4; ni++) {
                    mma16816(acc[mi][ni], ah[mi], bh[ni]);
                    mma16816(acc[mi][ni], ah[mi], bl[ni]);
                    mma16816(acc[mi][ni], al[mi], bh[ni]);
                }
        }
        __syncthreads();
    }

    // epilogue: add bias, store
#pragma unroll
    for (int mi = 0; mi < 4; mi++) {
        int row = rowBase + wm * 64 + mi * 16 + (lane >> 2);
#pragma unroll
        for (int ni = 0; ni < 4; ni++) {
            int col = colBase + wn * 32 + ni * 8 + (lane & 3) * 2;
            float b0 = bias[col], b1 = bias[col + 1];
            float2 v0 = make_float2(acc[mi][ni][0] + b0, acc[mi][ni][1] + b1);
            float2 v1 = make_float2(acc[mi][ni][2] + b0, acc[mi][ni][3] + b1);
            *reinterpret_cast<float2*>(&Cout[(size_t)row * 512 + col]) = v0;
            *reinterpret_cast<float2*>(&Cout[(size_t)(row + 8) * 512 + col]) = v1;
        }
    }
}

__global__ __launch_bounds__(256)
void gemm_qkv_mma(const float* __restrict__ bq, const float* __restrict__ bk,
                  const float* __restrict__ bv,
                  float* __restrict__ q, float* __restrict__ k, float* __restrict__ v)
{
    const int which = blockIdx.x >> 2;
    const int colBase = (blockIdx.x & 3) * 128;
    const float* bias = (which == 0) ? bq : (which == 1) ? bk : bv;
    float* C = (which == 0) ? q : (which == 1) ? k : v;
    gemm_mma_body(g_x_hi, g_x_lo,
                  g_w_hi + which * WSZ, g_w_lo + which * WSZ,
                  bias, C, blockIdx.y * 128, colBase);
}

__global__ __launch_bounds__(256)
void gemm_o_mma(const float* __restrict__ bo, float* __restrict__ out)
{
    gemm_mma_body(g_a_hi, g_a_lo,
                  g_w_hi + 3 * WSZ, g_w_lo + 3 * WSZ,
                  bo, out, blockIdx.y * 128, blockIdx.x * 128);
}

// ---------------- banded attention, two-pass key-per-lane ----------------
#define QT 32
#define KROWS 192
#define KSTRIDE 65
#define ATTN_SMEM ((KROWS * KSTRIDE + KROWS * 64 + QT * 64) * sizeof(float))

__global__ __launch_bounds__(128)
void attn_banded(const float* __restrict__ q, const float* __restrict__ k,
                 const float* __restrict__ v,
                 __nv_bfloat16* __restrict__ ohi, __nv_bfloat16* __restrict__ olo)
{
    extern __shared__ __align__(16) char dynsm[];
    float* sm = reinterpret_cast<float*>(dynsm);
    float* Ks = sm;                               // [192][65]
    float* Vs = sm + KROWS * KSTRIDE;             // [192][64]
    float* Qs = Vs + KROWS * 64;                  // [QT][64]

    const int h = blockIdx.y;
    const int base = blockIdx.x * QT;
    const int j0 = base - WINDOW;
    const int tid = threadIdx.x;

    for (int idx = tid; idx < KROWS * 16; idx += 128) {
        int r = idx >> 4, d4 = (idx & 15) * 4;
        int j = j0 + r;
        float4 kv = make_float4(0.f, 0.f, 0.f, 0.f);
        float4 vv = make_float4(0.f, 0.f, 0.f, 0.f);
        if (j >= 0 && j < S_LEN) {
            size_t g = (size_t)j * D_MODEL + h * D_K + d4;
            kv = *reinterpret_cast<const float4*>(&k[g]);
            vv = *reinterpret_cast<const float4*>(&v[g]);
        }
        float* kd = &Ks[r * KSTRIDE + d4];
        kd[0] = kv.x; kd[1] = kv.y; kd[2] = kv.z; kd[3] = kv.w;
        *reinterpret_cast<float4*>(&Vs[r * 64 + d4]) = vv;
    }
    for (int idx = tid; idx < QT * 16; idx += 128) {
        int ql = idx >> 4, d4 = (idx & 15) * 4;
        *reinterpret_cast<float4*>(&Qs[ql * 64 + d4]) =
            *reinterpret_cast<const float4*>(&q[(size_t)(base + ql) * D_MODEL + h * D_K + d4]);
    }
    __syncthreads();

    const int warp = tid >> 5;
    const int lane = tid & 31;

    for (int ql = warp; ql < QT; ql += 4) {
        const int s = base + ql;
        const int jlo = (s - WINDOW > 0) ? (s - WINDOW) : 0;
        const int jhi = (s + WINDOW < S_LEN - 1) ? (s + WINDOW) : (S_LEN - 1);
        const int nk = jhi - jlo + 1;
        const int rbase = jlo - j0;

        float s0 = 0.f, s1 = 0.f, s2 = 0.f, s3 = 0.f, s4 = 0.f;
        const float* kr = &Ks[(rbase + lane) * KSTRIDE];
        const float* qr = &Qs[ql * 64];
#pragma unroll 8
        for (int d = 0; d < 64; d++) {
            float qv = qr[d];
            s0 = fmaf(qv, kr[d], s0);
            s1 = fmaf(qv, kr[32 * KSTRIDE + d], s1);
            s2 = fmaf(qv, kr[64 * KSTRIDE + d], s2);
            s3 = fmaf(qv, kr[96 * KSTRIDE + d], s3);
            s4 = fmaf(qv, kr[128 * KSTRIDE + d], s4);
        }
        float sc[5] = { s0, s1, s2, s3, s4 };
        float m = -1e30f;
#pragma unroll
        for (int i = 0; i < 5; i++) {
            sc[i] = (lane + 32 * i < nk) ? sc[i] * SCALE : -1e30f;
            m = fmaxf(m, sc[i]);
        }
#pragma unroll
        for (int off = 16; off; off >>= 1)
            m = fmaxf(m, __shfl_xor_sync(0xffffffffu, m, off));
        float e[5];
        float l = 0.f;
#pragma unroll
        for (int i = 0; i < 5; i++) { e[i] = __expf(sc[i] - m); l += e[i]; }
#pragma unroll
        for (int off = 16; off; off >>= 1)
            l += __shfl_xor_sync(0xffffffffu, l, off);
        const float inv = 1.f / l;

        float a0 = 0.f, a1 = 0.f, b0 = 0.f, b1 = 0.f;
        const float* vb = &Vs[rbase * 64];
        if (nk == 129) {
#pragma unroll
            for (int slot = 0; slot < 4; slot++) {
                float ev = e[slot];
#pragma unroll
                for (int jj = 0; jj < 32; jj += 2) {
                    float p0 = __shfl_sync(0xffffffffu, ev, jj);
                    float p1 = __shfl_sync(0xffffffffu, ev, jj + 1);
                    const float* v0 = vb + (slot * 32 + jj) * 64;
                    a0 = fmaf(p0, v0[lane], a0);
                    a1 = fmaf(p0, v0[lane + 32], a1);
                    b0 = fmaf(p1, v0[64 + lane], b0);
                    b1 = fmaf(p1, v0[64 + lane + 32], b1);
                }
            }
            float p = __shfl_sync(0xffffffffu, e[4], 0);
            const float* v0 = vb + 128 * 64;
            a0 = fmaf(p, v0[lane], a0);
            a1 = fmaf(p, v0[lane + 32], a1);
        } else {
#pragma unroll
            for (int slot = 0; slot < 5; slot++) {
                int lim = nk - slot * 32;
                if (lim <= 0) break;
                if (lim > 32) lim = 32;
                float ev = e[slot];
                for (int jj = 0; jj < lim; jj++) {
                    float p = __shfl_sync(0xffffffffu, ev, jj);
                    const float* v0 = vb + (slot * 32 + jj) * 64;
                    a0 = fmaf(p, v0[lane], a0);
                    a1 = fmaf(p, v0[lane + 32], a1);
                }
            }
        }
        float o0 = (a0 + b0) * inv;
        float o1 = (a1 + b1) * inv;
        size_t gi = (size_t)s * D_MODEL + h * D_K + lane;
        __nv_bfloat16 h0 = __float2bfloat16(o0);
        __nv_bfloat16 h1 = __float2bfloat16(o1);
        ohi[gi] = h0;
        ohi[gi + 32] = h1;
        olo[gi] = __float2bfloat16(o0 - __bfloat162float(h0));
        olo[gi + 32] = __float2bfloat16(o1 - __bfloat162float(h1));
    }
}

// ---------------- launch ----------------
extern "C" void kernel_launch(void* const* d_in, const int* in_sizes, int n_in,
                              void* d_out, int out_size) {
    const float* x  = (const float*)d_in[0];
    const float* Wq = (const float*)d_in[1];
    const float* bq = (const float*)d_in[2];
    const float* Wk = (const float*)d_in[3];
    const float* bk = (const float*)d_in[4];
    const float* Wv = (const float*)d_in[5];
    const float* bv = (const float*)d_in[6];
    const float* Wo = (const float*)d_in[7];
    const float* bo = (const float*)d_in[8];
    float* out = (float*)d_out;

    float *gq, *gk, *gv;
    __nv_bfloat16 *gahi, *galo;
    cudaGetSymbolAddress((void**)&gq, g_q);
    cudaGetSymbolAddress((void**)&gk, g_k);
    cudaGetSymbolAddress((void**)&gv, g_v);
    cudaGetSymbolAddress((void**)&gahi, g_a_hi);
    cudaGetSymbolAddress((void**)&galo, g_a_lo);

    cudaFuncSetAttribute(gemm_qkv_mma, cudaFuncAttributeMaxDynamicSharedMemorySize, GSMEM);
    cudaFuncSetAttribute(gemm_o_mma, cudaFuncAttributeMaxDynamicSharedMemorySize, GSMEM);
    cudaFuncSetAttribute(attn_banded, cudaFuncAttributeMaxDynamicSharedMemorySize,
                         (int)ATTN_SMEM);

    convert_split<<<dim3(XSZ / (256 * 4), 5), 256>>>(x, Wq, Wk, Wv, Wo);

    gemm_qkv_mma<<<dim3(12, 16), 256, GSMEM>>>(bq, bk, bv, gq, gk, gv);

    attn_banded<<<dim3(S_LEN / QT, N_HEADS), 128, ATTN_SMEM>>>(gq, gk, gv, gahi, galo);

    gemm_o_mma<<<dim3(4, 16), 256, GSMEM>>>(bo, out);
}

// round 6
// speedup vs baseline: 4.7910x; 1.5517x over previous
#include <cuda_runtime.h>
#include <cuda_bf16.h>
#include <stdint.h>

#define S_LEN 2048
#define DM 512
#define NH 8
#define WIN 64
#define SCALE 0.125f
#define WSZ (512*512)
#define XSZ (2048*512)

// ---------------- scratch (no allocation allowed) ----------------
__device__ __align__(16) __nv_bfloat16 g_x_hi[XSZ], g_x_lo[XSZ];
__device__ __align__(16) __nv_bfloat16 g_w_hi[4 * WSZ], g_w_lo[4 * WSZ];
__device__ __align__(16) __nv_bfloat16 g_q_hi[XSZ], g_q_lo[XSZ];
__device__ __align__(16) __nv_bfloat16 g_k_hi[XSZ], g_k_lo[XSZ];
__device__ __align__(16) __nv_bfloat16 g_vt_hi[XSZ], g_vt_lo[XSZ];   // [512][2048]
__device__ __align__(16) __nv_bfloat16 g_a_hi[XSZ], g_a_lo[XSZ];

// ---------------- PTX helpers (baseline sm_80+, compile for compute_103) -----
__device__ __forceinline__ uint32_t smem_u32(const void* p) {
    uint32_t a;
    asm("{ .reg .u64 t; cvta.to.shared.u64 t, %1; cvt.u32.u64 %0, t; }"
        : "=r"(a) : "l"(p));
    return a;
}
__device__ __forceinline__ void cp16(uint32_t s, const void* g) {
    asm volatile("cp.async.cg.shared.global [%0], [%1], 16;"
                 :: "r"(s), "l"(g) : "memory");
}
__device__ __forceinline__ void cp_commit() {
    asm volatile("cp.async.commit_group;" ::: "memory");
}
template<int N> __device__ __forceinline__ void cp_wait() {
    asm volatile("cp.async.wait_group %0;" :: "n"(N) : "memory");
}
__device__ __forceinline__ void ldsm_x4(uint32_t& r0, uint32_t& r1,
                                        uint32_t& r2, uint32_t& r3, uint32_t a) {
    asm volatile("ldmatrix.sync.aligned.m8n8.x4.shared.b16 {%0,%1,%2,%3}, [%4];"
                 : "=r"(r0), "=r"(r1), "=r"(r2), "=r"(r3) : "r"(a));
}
__device__ __forceinline__ void mma16816(float c[4], const uint32_t a[4],
                                         const uint32_t b[2]) {
    asm volatile(
        "mma.sync.aligned.m16n8k16.row.col.f32.bf16.bf16.f32 "
        "{%0,%1,%2,%3}, {%4,%5,%6,%7}, {%8,%9}, {%0,%1,%2,%3};"
        : "+f"(c[0]), "+f"(c[1]), "+f"(c[2]), "+f"(c[3])
        : "r"(a[0]), "r"(a[1]), "r"(a[2]), "r"(a[3]), "r"(b[0]), "r"(b[1]));
}

// ---------------- split conversion: fp32 -> (bf16 hi, bf16 lo) ----------------
__global__ __launch_bounds__(256)
void convert_split(const float* __restrict__ x,
                   const float* __restrict__ wq, const float* __restrict__ wk,
                   const float* __restrict__ wv, const float* __restrict__ wo)
{
    const int tn = blockIdx.y;
    const float* src = (tn == 0) ? x : (tn == 1) ? wq : (tn == 2) ? wk
                       : (tn == 3) ? wv : wo;
    const int n = (tn == 0) ? XSZ : WSZ;
    __nv_bfloat16* hi = (tn == 0) ? g_x_hi : g_w_hi + (tn - 1) * WSZ;
    __nv_bfloat16* lo = (tn == 0) ? g_x_lo : g_w_lo + (tn - 1) * WSZ;

    int i4 = (blockIdx.x * 256 + threadIdx.x) * 4;
    if (i4 >= n) return;
    float4 v = *reinterpret_cast<const float4*>(&src[i4]);
    __nv_bfloat16 h0 = __float2bfloat16(v.x);
    __nv_bfloat16 h1 = __float2bfloat16(v.y);
    __nv_bfloat16 h2 = __float2bfloat16(v.z);
    __nv_bfloat16 h3 = __float2bfloat16(v.w);
    __nv_bfloat16 l0 = __float2bfloat16(v.x - __bfloat162float(h0));
    __nv_bfloat16 l1 = __float2bfloat16(v.y - __bfloat162float(h1));
    __nv_bfloat16 l2 = __float2bfloat16(v.z - __bfloat162float(h2));
    __nv_bfloat16 l3 = __float2bfloat16(v.w - __bfloat162float(h3));
    reinterpret_cast<__nv_bfloat162*>(hi + i4)[0] = __halves2bfloat162(h0, h1);
    reinterpret_cast<__nv_bfloat162*>(hi + i4)[1] = __halves2bfloat162(h2, h3);
    reinterpret_cast<__nv_bfloat162*>(lo + i4)[0] = __halves2bfloat162(l0, l1);
    reinterpret_cast<__nv_bfloat162*>(lo + i4)[1] = __halves2bfloat162(l2, l3);
}

// ---------------- split-bf16 GEMM: 64x128 C-tile per CTA ----------------------
// C = Ah·Bh^T + Ah·Bl^T + Al·Bh^T (+ bias). K streamed in 8 chunks of 64.
// SMEM rows: 64 bf16 = 128B, padded to 144B -> LDSM conflict-free.
#define KSTR 144
#define GAH 0
#define GAL 9216
#define GBH 18432
#define GBL 36864
#define GBUF 55296
#define GSMEM_B 110592

__device__ __forceinline__ void stage64(
    uint32_t sb, int buf, int c, int tid,
    const __nv_bfloat16* __restrict__ Ahi, const __nv_bfloat16* __restrict__ Alo,
    const __nv_bfloat16* __restrict__ Bhi, const __nv_bfloat16* __restrict__ Blo,
    int rowBase, int colBase)
{
#pragma unroll
    for (int i = 0; i < 12; i++) {
        int idx = tid + i * 256;
        const __nv_bfloat16* src; uint32_t off; int rbase; int rem;
        if (idx < 512)       { src = Ahi; off = GAH; rbase = rowBase; rem = idx; }
        else if (idx < 1024) { src = Alo; off = GAL; rbase = rowBase; rem = idx - 512; }
        else if (idx < 2048) { src = Bhi; off = GBH; rbase = colBase; rem = idx - 1024; }
        else                 { src = Blo; off = GBL; rbase = colBase; rem = idx - 2048; }
        int row = rem >> 3, cc = rem & 7;
        cp16(sb + (uint32_t)(buf * GBUF) + off + (uint32_t)(row * KSTR + cc * 16),
             src + ((size_t)(rbase + row) * DM + c * 64 + cc * 8));
    }
    cp_commit();
}

// mode: 0 = bf16 hi/lo [2048][512], 1 = bf16 hi/lo transposed [512][2048], 2 = fp32
__device__ __forceinline__ void gemm64(
    const __nv_bfloat16* __restrict__ Ahi, const __nv_bfloat16* __restrict__ Alo,
    const __nv_bfloat16* __restrict__ Bhi, const __nv_bfloat16* __restrict__ Blo,
    const float* __restrict__ bias, int mode,
    __nv_bfloat16* __restrict__ oHi, __nv_bfloat16* __restrict__ oLo,
    float* __restrict__ oF, int rowBase, int colBase)
{
    extern __shared__ __align__(16) char dynsm[];
    const uint32_t sb = smem_u32(dynsm);
    const int tid = threadIdx.x, lane = tid & 31, wid = tid >> 5;
    const int wm = wid >> 2, wn = wid & 3;          // warps: 2 (m) x 4 (n)
    const int a_row = (lane & 7) + ((lane >> 3) & 1) * 8, a_k = (lane >> 4) * 8;
    const int b_row = (lane & 7) + (lane >> 4) * 8,       b_k = ((lane >> 3) & 1) * 8;

    float acc[2][4][4] = {};

    stage64(sb, 0, 0, tid, Ahi, Alo, Bhi, Blo, rowBase, colBase);
    for (int c = 0; c < 8; c++) {
        if (c < 7) { stage64(sb, (c + 1) & 1, c + 1, tid, Ahi, Alo, Bhi, Blo,
                             rowBase, colBase); cp_wait<1>(); }
        else       { cp_wait<0>(); }
        __syncthreads();
        const uint32_t bb = sb + (uint32_t)((c & 1) * GBUF);
#pragma unroll
        for (int k16 = 0; k16 < 4; k16++) {
            uint32_t ah[2][4], al[2][4], bh[4][2], bl[4][2];
#pragma unroll
            for (int mi = 0; mi < 2; mi++) {
                uint32_t o = (uint32_t)((wm * 32 + mi * 16 + a_row) * KSTR +
                                        (k16 * 16 + a_k) * 2);
                ldsm_x4(ah[mi][0], ah[mi][1], ah[mi][2], ah[mi][3], bb + GAH + o);
                ldsm_x4(al[mi][0], al[mi][1], al[mi][2], al[mi][3], bb + GAL + o);
            }
#pragma unroll
            for (int bn = 0; bn < 2; bn++) {
                uint32_t o = (uint32_t)((wn * 32 + bn * 16 + b_row) * KSTR +
                                        (k16 * 16 + b_k) * 2);
                uint32_t r0, r1, r2, r3;
                ldsm_x4(r0, r1, r2, r3, bb + GBH + o);
                bh[bn * 2][0] = r0; bh[bn * 2][1] = r1;
                bh[bn * 2 + 1][0] = r2; bh[bn * 2 + 1][1] = r3;
                ldsm_x4(r0, r1, r2, r3, bb + GBL + o);
                bl[bn * 2][0] = r0; bl[bn * 2][1] = r1;
                bl[bn * 2 + 1][0] = r2; bl[bn * 2 + 1][1] = r3;
            }
#pragma unroll
            for (int mi = 0; mi < 2; mi++)
#pragma unroll
                for (int ni = 0; ni < 4; ni++) {
                    mma16816(acc[mi][ni], ah[mi], bh[ni]);
                    mma16816(acc[mi][ni], ah[mi], bl[ni]);
                    mma16816(acc[mi][ni], al[mi], bh[ni]);
                }
        }
        __syncthreads();
    }

#pragma unroll
    for (int mi = 0; mi < 2; mi++) {
        int row = rowBase + wm * 32 + mi * 16 + (lane >> 2);
#pragma unroll
        for (int ni = 0; ni < 4; ni++) {
            int col = colBase + wn * 32 + ni * 8 + (lane & 3) * 2;
            float b0 = bias[col], b1 = bias[col + 1];
            float v00 = acc[mi][ni][0] + b0, v01 = acc[mi][ni][1] + b1;
            float v10 = acc[mi][ni][2] + b0, v11 = acc[mi][ni][3] + b1;
            if (mode == 2) {
                *reinterpret_cast<float2*>(&oF[(size_t)row * DM + col]) =
                    make_float2(v00, v01);
                *reinterpret_cast<float2*>(&oF[(size_t)(row + 8) * DM + col]) =
                    make_float2(v10, v11);
            } else if (mode == 0) {
                __nv_bfloat16 h00 = __float2bfloat16(v00), h01 = __float2bfloat16(v01);
                __nv_bfloat16 h10 = __float2bfloat16(v10), h11 = __float2bfloat16(v11);
                *reinterpret_cast<__nv_bfloat162*>(&oHi[(size_t)row * DM + col]) =
                    __halves2bfloat162(h00, h01);
                *reinterpret_cast<__nv_bfloat162*>(&oHi[(size_t)(row + 8) * DM + col]) =
                    __halves2bfloat162(h10, h11);
                *reinterpret_cast<__nv_bfloat162*>(&oLo[(size_t)row * DM + col]) =
                    __halves2bfloat162(__float2bfloat16(v00 - __bfloat162float(h00)),
                                       __float2bfloat16(v01 - __bfloat162float(h01)));
                *reinterpret_cast<__nv_bfloat162*>(&oLo[(size_t)(row + 8) * DM + col]) =
                    __halves2bfloat162(__float2bfloat16(v10 - __bfloat162float(h10)),
                                       __float2bfloat16(v11 - __bfloat162float(h11)));
            } else {
                __nv_bfloat16 hh;
                hh = __float2bfloat16(v00);
                oHi[(size_t)col * S_LEN + row] = hh;
                oLo[(size_t)col * S_LEN + row] = __float2bfloat16(v00 - __bfloat162float(hh));
                hh = __float2bfloat16(v01);
                oHi[(size_t)(col + 1) * S_LEN + row] = hh;
                oLo[(size_t)(col + 1) * S_LEN + row] = __float2bfloat16(v01 - __bfloat162float(hh));
                hh = __float2bfloat16(v10);
                oHi[(size_t)col * S_LEN + row + 8] = hh;
                oLo[(size_t)col * S_LEN + row + 8] = __float2bfloat16(v10 - __bfloat162float(hh));
                hh = __float2bfloat16(v11);
                oHi[(size_t)(col + 1) * S_LEN + row + 8] = hh;
                oLo[(size_t)(col + 1) * S_LEN + row + 8] = __float2bfloat16(v11 - __bfloat162float(hh));
            }
        }
    }
}

__global__ __launch_bounds__(256, 2)
void gemm_qkv_mma(const float* __restrict__ bq, const float* __restrict__ bk,
                  const float* __restrict__ bv)
{
    const int which = blockIdx.x >> 2;
    const int colBase = (blockIdx.x & 3) * 128;
    const int rowBase = blockIdx.y * 64;
    const float* bias = (which == 0) ? bq : (which == 1) ? bk : bv;
    __nv_bfloat16 *oh, *ol; int mode;
    if (which == 0)      { oh = g_q_hi;  ol = g_q_lo;  mode = 0; }
    else if (which == 1) { oh = g_k_hi;  ol = g_k_lo;  mode = 0; }
    else                 { oh = g_vt_hi; ol = g_vt_lo; mode = 1; }
    gemm64(g_x_hi, g_x_lo, g_w_hi + which * WSZ, g_w_lo + which * WSZ,
           bias, mode, oh, ol, nullptr, rowBase, colBase);
}

__global__ __launch_bounds__(256, 2)
void gemm_o_mma(const float* __restrict__ bo, float* __restrict__ out)
{
    gemm64(g_a_hi, g_a_lo, g_w_hi + 3 * WSZ, g_w_lo + 3 * WSZ,
           bo, 2, nullptr, nullptr, out, blockIdx.y * 64, blockIdx.x * 128);
}

// ---------------- tensor-core banded attention ------------------------------
// Block = (64 queries, 1 head). Keys window 192. S = Q·K^T (3-term split mma),
// masked fp32 softmax in smem, O = P·V (3-term split mma, P pre-normalized).
#define AQH 0
#define AQL 9216
#define AKH 18432
#define AKL 46080
#define AVH 73728
#define AVL 99328
#define ASF 124928
#define APH AKH              /* P overlays K after S is computed */
#define APL AKL
#define ATTN_B 176128

__global__ __launch_bounds__(256)
void attn_mma()
{
    extern __shared__ __align__(16) char dynsm[];
    const uint32_t sb = smem_u32(dynsm);
    const int tid = threadIdx.x, lane = tid & 31, wid = tid >> 5;
    const int h = blockIdx.y;
    const int base = blockIdx.x * 64;
    const int j0 = base - WIN;

    // ---- stage Q [64][64], K [192][64], V^T [64][192] (hi+lo each) ----
#pragma unroll
    for (int i = 0; i < 4; i++) {                       // Q
        int idx = tid + i * 256;
        int arr = idx >> 9, rem = idx & 511;
        int row = rem >> 3, cc = rem & 7;
        cp16(sb + (arr ? AQL : AQH) + (uint32_t)(row * 144 + cc * 16),
             (arr ? g_q_lo : g_q_hi) + ((size_t)(base + row) * DM + h * 64 + cc * 8));
    }
#pragma unroll
    for (int i = 0; i < 12; i++) {                      // K
        int idx = tid + i * 256;
        int arr = idx >= 1536 ? 1 : 0, rem = arr ? idx - 1536 : idx;
        int row = rem >> 3, cc = rem & 7;
        int j = j0 + row;
        uint32_t off = (arr ? AKL : AKH) + (uint32_t)(row * 144 + cc * 16);
        if (j >= 0 && j < S_LEN)
            cp16(sb + off, (arr ? g_k_lo : g_k_hi) + ((size_t)j * DM + h * 64 + cc * 8));
        else
            *reinterpret_cast<uint4*>(dynsm + off) = make_uint4(0, 0, 0, 0);
    }
#pragma unroll
    for (int i = 0; i < 12; i++) {                      // V^T
        int idx = tid + i * 256;
        int arr = idx >= 1536 ? 1 : 0, rem = arr ? idx - 1536 : idx;
        int row = rem / 24, cc = rem % 24;
        int j = j0 + cc * 8;
        uint32_t off = (arr ? AVL : AVH) + (uint32_t)(row * 400 + cc * 16);
        if (j >= 0 && j + 8 <= S_LEN)
            cp16(sb + off, (arr ? g_vt_lo : g_vt_hi) + ((size_t)(h * 64 + row) * S_LEN + j));
        else
            *reinterpret_cast<uint4*>(dynsm + off) = make_uint4(0, 0, 0, 0);
    }
    cp_commit();
    cp_wait<0>();
    __syncthreads();

    const int a_row = (lane & 7) + ((lane >> 3) & 1) * 8, a_k = (lane >> 4) * 8;
    const int b_row = (lane & 7) + (lane >> 4) * 8,       b_k = ((lane >> 3) & 1) * 8;
    const int wm = wid >> 1, wn = wid & 1;   // warps: 4 (m16) x 2 (n96 / n32)

    // ---- phase B: S = Q·K^T ----
    {
        float sacc[12][4] = {};
#pragma unroll
        for (int k16 = 0; k16 < 4; k16++) {
            uint32_t ah[4], al[4];
            uint32_t oA = (uint32_t)((wm * 16 + a_row) * 144 + (k16 * 16 + a_k) * 2);
            ldsm_x4(ah[0], ah[1], ah[2], ah[3], sb + AQH + oA);
            ldsm_x4(al[0], al[1], al[2], al[3], sb + AQL + oA);
#pragma unroll
            for (int t = 0; t < 6; t++) {
                uint32_t oB = (uint32_t)((wn * 96 + t * 16 + b_row) * 144 +
                                         (k16 * 16 + b_k) * 2);
                uint32_t r0, r1, r2, r3, b0[2], b1[2], c0[2], c1[2];
                ldsm_x4(r0, r1, r2, r3, sb + AKH + oB);
                b0[0] = r0; b0[1] = r1; b1[0] = r2; b1[1] = r3;
                ldsm_x4(r0, r1, r2, r3, sb + AKL + oB);
                c0[0] = r0; c0[1] = r1; c1[0] = r2; c1[1] = r3;
                mma16816(sacc[t * 2], ah, b0);
                mma16816(sacc[t * 2], ah, c0);
                mma16816(sacc[t * 2], al, b0);
                mma16816(sacc[t * 2 + 1], ah, b1);
                mma16816(sacc[t * 2 + 1], ah, c1);
                mma16816(sacc[t * 2 + 1], al, b1);
            }
        }
        float* S = reinterpret_cast<float*>(dynsm + ASF);
        int row = wm * 16 + (lane >> 2);
#pragma unroll
        for (int t = 0; t < 12; t++) {
            int col = wn * 96 + t * 8 + (lane & 3) * 2;
            *reinterpret_cast<float2*>(&S[row * 200 + col]) =
                make_float2(sacc[t][0], sacc[t][1]);
            *reinterpret_cast<float2*>(&S[(row + 8) * 200 + col]) =
                make_float2(sacc[t][2], sacc[t][3]);
        }
    }
    __syncthreads();

    // ---- masked softmax rows; write normalized P (bf16 hi/lo) over K ----
    {
        float* S = reinterpret_cast<float*>(dynsm + ASF);
#pragma unroll
        for (int r8 = 0; r8 < 8; r8++) {
            int m = wid * 8 + r8;
            int nlo = m, nhi = m + 128;
            if (-j0 > nlo) nlo = -j0;
            if (2047 - j0 < nhi) nhi = 2047 - j0;
            float v[6], mx = -1e30f;
#pragma unroll
            for (int i = 0; i < 6; i++) {
                int n = lane + 32 * i;
                float sv = S[m * 200 + n] * SCALE;
                v[i] = (n >= nlo && n <= nhi) ? sv : -1e30f;
                mx = fmaxf(mx, v[i]);
            }
#pragma unroll
            for (int o = 16; o; o >>= 1)
                mx = fmaxf(mx, __shfl_xor_sync(0xffffffffu, mx, o));
            float e[6], sum = 0.f;
#pragma unroll
            for (int i = 0; i < 6; i++) { e[i] = __expf(v[i] - mx); sum += e[i]; }
#pragma unroll
            for (int o = 16; o; o >>= 1)
                sum += __shfl_xor_sync(0xffffffffu, sum, o);
            float inv = 1.f / sum;
#pragma unroll
            for (int i = 0; i < 6; i++) {
                int n = lane + 32 * i;
                float p = e[i] * inv;
                __nv_bfloat16 ph = __float2bfloat16(p);
                __nv_bfloat16 pl = __float2bfloat16(p - __bfloat162float(ph));
                *reinterpret_cast<__nv_bfloat16*>(dynsm + APH + m * 400 + n * 2) = ph;
                *reinterpret_cast<__nv_bfloat16*>(dynsm + APL + m * 400 + n * 2) = pl;
            }
        }
    }
    __syncthreads();

    // ---- phase C: O = P·V ----
    {
        float oacc[4][4] = {};
#pragma unroll
        for (int k16 = 0; k16 < 12; k16++) {
            uint32_t ph[4], pl[4];
            uint32_t oA = (uint32_t)((wm * 16 + a_row) * 400 + (k16 * 16 + a_k) * 2);
            ldsm_x4(ph[0], ph[1], ph[2], ph[3], sb + APH + oA);
            ldsm_x4(pl[0], pl[1], pl[2], pl[3], sb + APL + oA);
#pragma unroll
            for (int bn = 0; bn < 2; bn++) {
                uint32_t oB = (uint32_t)((wn * 32 + bn * 16 + b_row) * 400 +
                                         (k16 * 16 + b_k) * 2);
                uint32_t r0, r1, r2, r3, vh0[2], vh1[2], vl0[2], vl1[2];
                ldsm_x4(r0, r1, r2, r3, sb + AVH + oB);
                vh0[0] = r0; vh0[1] = r1; vh1[0] = r2; vh1[1] = r3;
                ldsm_x4(r0, r1, r2, r3, sb + AVL + oB);
                vl0[0] = r0; vl0[1] = r1; vl1[0] = r2; vl1[1] = r3;
                mma16816(oacc[bn * 2], ph, vh0);
                mma16816(oacc[bn * 2], ph, vl0);
                mma16816(oacc[bn * 2], pl, vh0);
                mma16816(oacc[bn * 2 + 1], ph, vh1);
                mma16816(oacc[bn * 2 + 1], ph, vl1);
                mma16816(oacc[bn * 2 + 1], pl, vh1);
            }
        }
        int row = base + wm * 16 + (lane >> 2);
#pragma unroll
        for (int t = 0; t < 4; t++) {
            int col = h * 64 + wn * 32 + t * 8 + (lane & 3) * 2;
            float v00 = oacc[t][0], v01 = oacc[t][1];
            float v10 = oacc[t][2], v11 = oacc[t][3];
            __nv_bfloat16 h00 = __float2bfloat16(v00), h01 = __float2bfloat16(v01);
            __nv_bfloat16 h10 = __float2bfloat16(v10), h11 = __float2bfloat16(v11);
            *reinterpret_cast<__nv_bfloat162*>(&g_a_hi[(size_t)row * DM + col]) =
                __halves2bfloat162(h00, h01);
            *reinterpret_cast<__nv_bfloat162*>(&g_a_hi[(size_t)(row + 8) * DM + col]) =
                __halves2bfloat162(h10, h11);
            *reinterpret_cast<__nv_bfloat162*>(&g_a_lo[(size_t)row * DM + col]) =
                __halves2bfloat162(__float2bfloat16(v00 - __bfloat162float(h00)),
                                   __float2bfloat16(v01 - __bfloat162float(h01)));
            *reinterpret_cast<__nv_bfloat162*>(&g_a_lo[(size_t)(row + 8) * DM + col]) =
                __halves2bfloat162(__float2bfloat16(v10 - __bfloat162float(h10)),
                                   __float2bfloat16(v11 - __bfloat162float(h11)));
        }
    }
}

// ---------------- launch ----------------
extern "C" void kernel_launch(void* const* d_in, const int* in_sizes, int n_in,
                              void* d_out, int out_size) {
    const float* x  = (const float*)d_in[0];
    const float* Wq = (const float*)d_in[1];
    const float* bq = (const float*)d_in[2];
    const float* Wk = (const float*)d_in[3];
    const float* bk = (const float*)d_in[4];
    const float* Wv = (const float*)d_in[5];
    const float* bv = (const float*)d_in[6];
    const float* Wo = (const float*)d_in[7];
    const float* bo = (const float*)d_in[8];
    float* out = (float*)d_out;

    cudaFuncSetAttribute(gemm_qkv_mma, cudaFuncAttributeMaxDynamicSharedMemorySize, GSMEM_B);
    cudaFuncSetAttribute(gemm_o_mma, cudaFuncAttributeMaxDynamicSharedMemorySize, GSMEM_B);
    cudaFuncSetAttribute(attn_mma, cudaFuncAttributeMaxDynamicSharedMemorySize, ATTN_B);

    convert_split<<<dim3(XSZ / 1024, 5), 256>>>(x, Wq, Wk, Wv, Wo);

    gemm_qkv_mma<<<dim3(12, 32), 256, GSMEM_B>>>(bq, bk, bv);

    attn_mma<<<dim3(32, 8), 256, ATTN_B>>>();

    gemm_o_mma<<<dim3(4, 32), 256, GSMEM_B>>>(bo, out);
}